// round 3
// baseline (speedup 1.0000x reference)
#include <cuda_runtime.h>

#define NUM_CLASSES 1000
#define FEAT_DIM 512
#define BATCH 65536
#define THREADS 512
#define WARPS_PER_BLOCK (THREADS / 32)
#define NBLOCKS (BATCH / WARPS_PER_BLOCK)   // 4096

// Scratch — zero-initialized at module load; the kernel's finishing block
// restores them to zero at the end of every execution (self-resetting), so
// the "zero at entry" invariant holds across graph replays.
__device__ float g_sums[NUM_CLASSES];
__device__ int g_cnt[NUM_CLASSES];
__device__ unsigned int g_ticket;

__device__ __forceinline__ float ldcg_f(const float* p) {
    float v;
    asm volatile("ld.global.cg.f32 %0, [%1];" : "=f"(v) : "l"(p));
    return v;
}
__device__ __forceinline__ int ldcg_i(const int* p) {
    int v;
    asm volatile("ld.global.cg.s32 %0, [%1];" : "=r"(v) : "l"(p));
    return v;
}

__global__ void __launch_bounds__(THREADS) cl_fused_kernel(
    const float* __restrict__ features,
    const float* __restrict__ centers,
    const long long* __restrict__ labels,
    float* __restrict__ out)
{
    __shared__ float red[WARPS_PER_BLOCK];
    __shared__ unsigned int s_ticket;

    int warp = threadIdx.x >> 5;
    int lane = threadIdx.x & 31;
    int row = blockIdx.x * WARPS_PER_BLOCK + warp;

    int lab = (int)labels[row];  // warp-uniform broadcast load

    const float4* frow = reinterpret_cast<const float4*>(features + (size_t)row * FEAT_DIM);
    const float4* crow = reinterpret_cast<const float4*>(centers + (size_t)lab * FEAT_DIM);

    float acc = 0.0f;
#pragma unroll
    for (int i = 0; i < 4; i++) {
        float4 a = __ldcs(frow + lane + i * 32);  // evict-first: protect L2 for centers
        float4 b = __ldg(crow + lane + i * 32);   // cached: centers stay L2/L1 resident
        float dx = a.x - b.x;
        float dy = a.y - b.y;
        float dz = a.z - b.z;
        float dw = a.w - b.w;
        acc += dx * dx + dy * dy + dz * dz + dw * dw;
    }

#pragma unroll
    for (int o = 16; o; o >>= 1)
        acc += __shfl_xor_sync(0xffffffffu, acc, o);

    if (lane == 0) {
        atomicAdd(&g_sums[lab], acc);
        atomicAdd(&g_cnt[lab], 1);
    }

    // ---- last-block-done finish ----
    __syncthreads();
    if (threadIdx.x == 0) {
        __threadfence();  // make this block's atomics visible before ticking
        s_ticket = atomicAdd(&g_ticket, 1u);
    }
    __syncthreads();
    if (s_ticket != NBLOCKS - 1) return;

    // We are the last block: every other block has fenced + ticked, so all
    // g_sums/g_cnt updates are globally visible. Read via .cg (bypass L1).
    __threadfence();

    int tid = threadIdx.x;
    float v = 0.0f;
    for (int c = tid; c < NUM_CLASSES; c += THREADS) {
        int cnt = ldcg_i(&g_cnt[c]);
        if (cnt > 0)
            v += ldcg_f(&g_sums[c]) / ((float)cnt * (float)FEAT_DIM);
        // reset scratch for the next graph replay
        g_sums[c] = 0.0f;
        g_cnt[c] = 0;
    }

#pragma unroll
    for (int o = 16; o; o >>= 1)
        v += __shfl_xor_sync(0xffffffffu, v, o);
    if (lane == 0) red[warp] = v;
    __syncthreads();

    if (warp == 0) {
        v = (lane < WARPS_PER_BLOCK) ? red[lane] : 0.0f;
#pragma unroll
        for (int o = 8; o; o >>= 1)
            v += __shfl_xor_sync(0xffffffffu, v, o);
        if (lane == 0) {
            out[0] = v / (float)BATCH;
            g_ticket = 0u;  // reset ticket for next replay
        }
    }
}

extern "C" void kernel_launch(void* const* d_in, const int* in_sizes, int n_in,
                              void* d_out, int out_size) {
    const float* features = (const float*)d_in[0];
    const float* centers = (const float*)d_in[1];
    const long long* labels = (const long long*)d_in[2];
    float* out = (float*)d_out;

    cl_fused_kernel<<<NBLOCKS, THREADS>>>(features, centers, labels, out);
}

// round 4
// speedup vs baseline: 2.1088x; 2.1088x over previous
#include <cuda_runtime.h>

#define NUM_CLASSES 1000
#define FEAT_DIM 512
#define BATCH 65536
#define HIST_BLOCKS 64
#define HIST_THREADS 256
#define THREADS 512
#define WARPS_PER_BLOCK (THREADS / 32)
#define NBLOCKS (BATCH / WARPS_PER_BLOCK)   // 4096

// Scratch — zero at module load; main kernel's last block self-resets them,
// so the "zero at entry" invariant holds across graph replays.
__device__ int g_cnt[NUM_CLASSES];
__device__ unsigned int g_ticket;

// K1: label histogram (privatized smem) + zero the (poisoned) output scalar.
__global__ void __launch_bounds__(HIST_THREADS) cl_hist_kernel(
    const long long* __restrict__ labels,
    float* __restrict__ out)
{
    __shared__ int h[NUM_CLASSES];
    for (int c = threadIdx.x; c < NUM_CLASSES; c += HIST_THREADS) h[c] = 0;
    if (blockIdx.x == 0 && threadIdx.x == 0) out[0] = 0.0f;
    __syncthreads();

    // Each block covers BATCH/HIST_BLOCKS = 1024 labels; 4 per thread.
    const longlong2* lab2 =
        reinterpret_cast<const longlong2*>(labels + (size_t)blockIdx.x * (BATCH / HIST_BLOCKS));
#pragma unroll
    for (int i = 0; i < 2; i++) {
        longlong2 v = lab2[threadIdx.x * 2 + i];
        atomicAdd(&h[(int)v.x], 1);
        atomicAdd(&h[(int)v.y], 1);
    }
    __syncthreads();

    for (int c = threadIdx.x; c < NUM_CLASSES; c += HIST_THREADS) {
        int n = h[c];
        if (n) atomicAdd(&g_cnt[c], n);
    }
}

// K2: one warp per row; streaming feature loads, cached center loads,
// per-warp weight from precomputed counts, ONE atomic per block to out[0].
// Last block (ticket) resets g_cnt + ticket for the next graph replay.
__global__ void __launch_bounds__(THREADS) cl_main_kernel(
    const float* __restrict__ features,
    const float* __restrict__ centers,
    const long long* __restrict__ labels,
    float* __restrict__ out)
{
    __shared__ float red[WARPS_PER_BLOCK];
    __shared__ unsigned int s_ticket;

    int warp = threadIdx.x >> 5;
    int lane = threadIdx.x & 31;
    int row = blockIdx.x * WARPS_PER_BLOCK + warp;

    int lab = (int)labels[row];  // warp-uniform broadcast load

    const float4* frow = reinterpret_cast<const float4*>(features + (size_t)row * FEAT_DIM);
    const float4* crow = reinterpret_cast<const float4*>(centers + (size_t)lab * FEAT_DIM);

    float acc = 0.0f;
#pragma unroll
    for (int i = 0; i < 4; i++) {
        float4 a = __ldcs(frow + lane + i * 32);  // evict-first: protect L2 for centers
        float4 b = __ldg(crow + lane + i * 32);   // cached: centers stay L2-resident
        float dx = a.x - b.x;
        float dy = a.y - b.y;
        float dz = a.z - b.z;
        float dw = a.w - b.w;
        acc += dx * dx + dy * dy + dz * dz + dw * dw;
    }

#pragma unroll
    for (int o = 16; o; o >>= 1)
        acc += __shfl_xor_sync(0xffffffffu, acc, o);

    if (lane == 0) {
        int cnt = g_cnt[lab];  // >= 1, precomputed by K1
        float w = __fdividef(1.0f, (float)cnt * (float)FEAT_DIM) * (1.0f / (float)BATCH);
        red[warp] = acc * w;
    }
    __syncthreads();

    if (warp == 0) {
        float v = (lane < WARPS_PER_BLOCK) ? red[lane] : 0.0f;
#pragma unroll
        for (int o = 8; o; o >>= 1)
            v += __shfl_xor_sync(0xffffffffu, v, o);
        if (lane == 0)
            atomicAdd(out, v);
    }

    // ---- last-block self-reset of scratch (for next graph replay) ----
    __syncthreads();
    if (threadIdx.x == 0) {
        __threadfence();  // order this block's g_cnt reads / out-atomic before ticking
        s_ticket = atomicAdd(&g_ticket, 1u);
    }
    __syncthreads();
    if (s_ticket != NBLOCKS - 1) return;

    for (int c = threadIdx.x; c < NUM_CLASSES; c += THREADS)
        g_cnt[c] = 0;
    if (threadIdx.x == 0)
        g_ticket = 0u;
}

extern "C" void kernel_launch(void* const* d_in, const int* in_sizes, int n_in,
                              void* d_out, int out_size) {
    const float* features = (const float*)d_in[0];
    const float* centers = (const float*)d_in[1];
    const long long* labels = (const long long*)d_in[2];
    float* out = (float*)d_out;

    cl_hist_kernel<<<HIST_BLOCKS, HIST_THREADS>>>(labels, out);
    cl_main_kernel<<<NBLOCKS, THREADS>>>(features, centers, labels, out);
}

// round 5
// speedup vs baseline: 2.4399x; 1.1570x over previous
#include <cuda_runtime.h>

#define NUM_CLASSES 1000
#define FEAT_DIM 512
#define BATCH 65536
#define NSLAB 32
#define HIST_THREADS 256
#define THREADS 512
#define WARPS_PER_BLOCK (THREADS / 32)
#define NBLOCKS (BATCH / WARPS_PER_BLOCK)   // 4096

// Per-block partial histograms, transposed: g_part[class][slab].
// Fully overwritten by K1 every call -> no reset, no atomics, deterministic.
__device__ int g_part[NUM_CLASSES * NSLAB];

// K1: 32 blocks; each builds a private smem histogram of its 2048 labels and
// stores it into its slab column with plain STGs. Block 0 zeroes out[0].
__global__ void __launch_bounds__(HIST_THREADS) cl_hist_kernel(
    const long long* __restrict__ labels,
    float* __restrict__ out)
{
    __shared__ int h[NUM_CLASSES];
    for (int c = threadIdx.x; c < NUM_CLASSES; c += HIST_THREADS) h[c] = 0;
    if (blockIdx.x == 0 && threadIdx.x == 0) out[0] = 0.0f;
    __syncthreads();

    // Each block covers BATCH/NSLAB = 2048 labels; 8 per thread via longlong2.
    const longlong2* lab2 =
        reinterpret_cast<const longlong2*>(labels + (size_t)blockIdx.x * (BATCH / NSLAB));
#pragma unroll
    for (int i = 0; i < 4; i++) {
        longlong2 v = lab2[threadIdx.x * 4 + i];
        atomicAdd(&h[(int)v.x], 1);
        atomicAdd(&h[(int)v.y], 1);
    }
    __syncthreads();

    int b = blockIdx.x;
    for (int c = threadIdx.x; c < NUM_CLASSES; c += HIST_THREADS)
        g_part[c * NSLAB + b] = h[c];
}

// K2: one warp per row. Streaming feature loads, cached center loads.
// Count for the row's label = sum of its 32 slab entries (one coalesced
// 128B line per warp, heavily reused across same-label warps -> L1 hits).
// One un-fenced atomicAdd(out) per block. No scratch mutation -> replay-safe.
__global__ void __launch_bounds__(THREADS) cl_main_kernel(
    const float* __restrict__ features,
    const float* __restrict__ centers,
    const long long* __restrict__ labels,
    float* __restrict__ out)
{
    __shared__ float red[WARPS_PER_BLOCK];

    int warp = threadIdx.x >> 5;
    int lane = threadIdx.x & 31;
    int row = blockIdx.x * WARPS_PER_BLOCK + warp;

    int lab = (int)labels[row];  // warp-uniform broadcast load

    // Kick off the count-partials load early; latency hides under the stream.
    int cnt = __ldg(&g_part[lab * NSLAB + lane]);

    const float4* frow = reinterpret_cast<const float4*>(features + (size_t)row * FEAT_DIM);
    const float4* crow = reinterpret_cast<const float4*>(centers + (size_t)lab * FEAT_DIM);

    float acc = 0.0f;
#pragma unroll
    for (int i = 0; i < 4; i++) {
        float4 a = __ldcs(frow + lane + i * 32);  // evict-first: protect L2 for centers
        float4 b = __ldg(crow + lane + i * 32);   // cached: centers stay L1/L2 resident
        float dx = a.x - b.x;
        float dy = a.y - b.y;
        float dz = a.z - b.z;
        float dw = a.w - b.w;
        acc += dx * dx + dy * dy + dz * dz + dw * dw;
    }

#pragma unroll
    for (int o = 16; o; o >>= 1) {
        acc += __shfl_xor_sync(0xffffffffu, acc, o);
        cnt += __shfl_xor_sync(0xffffffffu, cnt, o);
    }

    if (lane == 0) {
        float w = __fdividef(1.0f, (float)cnt * (float)FEAT_DIM) * (1.0f / (float)BATCH);
        red[warp] = acc * w;
    }
    __syncthreads();

    if (warp == 0) {
        float v = (lane < WARPS_PER_BLOCK) ? red[lane] : 0.0f;
#pragma unroll
        for (int o = 8; o; o >>= 1)
            v += __shfl_xor_sync(0xffffffffu, v, o);
        if (lane == 0)
            atomicAdd(out, v);
    }
}

extern "C" void kernel_launch(void* const* d_in, const int* in_sizes, int n_in,
                              void* d_out, int out_size) {
    const float* features = (const float*)d_in[0];
    const float* centers = (const float*)d_in[1];
    const long long* labels = (const long long*)d_in[2];
    float* out = (float*)d_out;

    cl_hist_kernel<<<NSLAB, HIST_THREADS>>>(labels, out);
    cl_main_kernel<<<NBLOCKS, THREADS>>>(features, centers, labels, out);
}